// round 5
// baseline (speedup 1.0000x reference)
#include <cuda_runtime.h>
#include <math.h>

#define B_   16
#define L_   1534
#define C_   16
#define SZ_  512
#define O1_  1023
#define O2_  512
#define EPS_ 1e-3f
#define NBLK 128

// Scratch + barrier state (no allocations allowed)
__device__ __align__(16) float g_h1t[(O1_ + 1) * B_];   // h1 transposed: [o][b]
__device__ __align__(16) float g_h2t[O2_ * B_];         // h2 transposed: [o][b]
__device__ float g_gate[B_];
__device__ unsigned g_bar_count = 0;
__device__ volatile unsigned g_bar_gen = 0;

__device__ __forceinline__ void fma2(unsigned long long& d,
                                     unsigned long long a,
                                     unsigned long long b) {
    asm("fma.rn.f32x2 %0, %1, %2, %0;" : "+l"(d) : "l"(a), "l"(b));
}
__device__ __forceinline__ float2 unpack2(unsigned long long v) {
    float2 r;
    asm("mov.b64 {%0, %1}, %2;" : "=f"(r.x), "=f"(r.y) : "l"(v));
    return r;
}

// gpu-scope grid barrier: all NBLK blocks are co-resident (NBLK < #SMs).
__device__ __forceinline__ void grid_sync() {
    __syncthreads();
    if (threadIdx.x == 0) {
        unsigned gen = g_bar_gen;
        __threadfence();                         // publish this block's writes
        if (atomicAdd(&g_bar_count, 1u) == NBLK - 1u) {
            atomicExch(&g_bar_count, 0u);
            __threadfence();
            atomicAdd((unsigned*)&g_bar_gen, 1u);
        } else {
            while (g_bar_gen == gen) __nanosleep(64);
        }
        __threadfence();                         // acquire (invalidates L1)
    }
    __syncthreads();
}

// ---------------------------------------------------------------------------
// One persistent kernel, 128 blocks x 256 threads, 4 stages + 3 grid barriers.
//
// Stage 1: h1[o][b] = elu( sum_{s,c} x[b,o+s,c]*W1[o,s,c] + b1[o] )
//   Block: 8 o's. 8 warps = kh(4) x bq(2). lane: cq = lane&3, rp = lane>>2.
//   Thread: no=8 o's x nb=8 batches (8bq..8bq+7); kh quarters the 65-chunk
//   reduction d = rp + 8k (k=0 prologue, k=1..63 interior, k=64 epilogue).
//   acc[o][b] = one f32x2 (c01+c23 products folded together). W1 L1 traffic
//   2x (bq only), x traffic 1x -> ~1.03 MB/block; LDG.128 ~2k/block.
// ---------------------------------------------------------------------------
__global__ void __launch_bounds__(256, 1)
k_fused(const float* __restrict__ x,  const float* __restrict__ W1,
        const float* __restrict__ b1, const float* __restrict__ W2,
        const float* __restrict__ b2, const float* __restrict__ Wl,
        const float* __restrict__ bl, const float* __restrict__ Ws,
        const float* __restrict__ bs, const float* __restrict__ gamma,
        const float* __restrict__ beta,const float* __restrict__ mm,
        const float* __restrict__ mv, float* __restrict__ out) {
    const int t    = threadIdx.x;
    const int bid  = blockIdx.x;
    const int lane = t & 31;
    const int warp = t >> 5;
    const int cq   = lane & 3;
    const int rp   = lane >> 2;
    const int bq   = warp & 1;        // batch half: 8bq .. 8bq+7
    const int kh   = warp >> 1;       // reduction quarter 0..3

    __shared__ float red[64][68];     // stage1 reduction scratch

    // ================= STAGE 1 =================
    {
        const int  o0   = bid * 8;
        const bool full = (o0 + 8 <= O1_);

        unsigned long long acc[8][8];
#pragma unroll
        for (int o = 0; o < 8; o++)
#pragma unroll
            for (int i = 0; i < 8; i++) acc[o][i] = 0ull;

        // k ranges: kh0: prologue(k=0) + k=1..16; kh1: 17..32; kh2: 33..48;
        //           kh3: 49..63 + epilogue(k=64)
        const int k0   = (kh == 0) ? 0 : (16 * kh + 1);
        const int kint = (kh == 3) ? 15 : 16;

        const float* bx = x  + ((8 * bq) * L_ + o0 + rp) * 16 + 4 * cq + k0 * 128;
        const float* bw = W1 + o0 * (SZ_ * C_) + rp * 16 + 4 * cq + k0 * 128;

        // ---- prologue (kh==0), d = rp: valid o <= rp ----
        if (kh == 0) {
            ulonglong2 xv[8];
#pragma unroll
            for (int i = 0; i < 8; i++)
                xv[i] = *(const ulonglong2*)(bx + i * (L_ * 16));
#pragma unroll
            for (int o = 0; o < 8; o++) {
                if (o <= rp && o0 + o < O1_) {
                    ulonglong2 wv = *(const ulonglong2*)(bw + o * 8176);
#pragma unroll
                    for (int i = 0; i < 8; i++) {
                        fma2(acc[o][i], wv.x, xv[i].x);
                        fma2(acc[o][i], wv.y, xv[i].y);
                    }
                }
            }
            bx += 128; bw += 128;
        }

        // ---- interior: all 8 o valid ----
        if (full) {
#pragma unroll 1
            for (int k = 0; k < kint; k++) {
                ulonglong2 xv[8];
#pragma unroll
                for (int i = 0; i < 8; i++)
                    xv[i] = *(const ulonglong2*)(bx + i * (L_ * 16));
#pragma unroll
                for (int o = 0; o < 8; o++) {
                    ulonglong2 wv = *(const ulonglong2*)(bw + o * 8176);
#pragma unroll
                    for (int i = 0; i < 8; i++) {
                        fma2(acc[o][i], wv.x, xv[i].x);
                        fma2(acc[o][i], wv.y, xv[i].y);
                    }
                }
                bx += 128; bw += 128;
            }
        } else {
#pragma unroll 1
            for (int k = 0; k < kint; k++) {
                ulonglong2 xv[8];
#pragma unroll
                for (int i = 0; i < 8; i++)
                    xv[i] = *(const ulonglong2*)(bx + i * (L_ * 16));
#pragma unroll
                for (int o = 0; o < 8; o++) {
                    if (o0 + o < O1_) {
                        ulonglong2 wv = *(const ulonglong2*)(bw + o * 8176);
#pragma unroll
                        for (int i = 0; i < 8; i++) {
                            fma2(acc[o][i], wv.x, xv[i].x);
                            fma2(acc[o][i], wv.y, xv[i].y);
                        }
                    }
                }
                bx += 128; bw += 128;
            }
        }

        // ---- epilogue (kh==3), d = 512+rp: valid o > rp ----
        if (kh == 3) {
            int row = o0 + 512 + rp;
            if (row > L_ - 1) row = L_ - 1;   // clamped slots only hit masked o's
            const float* ex = x + ((8 * bq) * L_ + row) * 16 + 4 * cq;
            ulonglong2 xv[8];
#pragma unroll
            for (int i = 0; i < 8; i++)
                xv[i] = *(const ulonglong2*)(ex + i * (L_ * 16));
#pragma unroll
            for (int o = 0; o < 8; o++) {
                if (o > rp && o0 + o < O1_) {
                    ulonglong2 wv = *(const ulonglong2*)(bw + o * 8176);
#pragma unroll
                    for (int i = 0; i < 8; i++) {
                        fma2(acc[o][i], wv.x, xv[i].x);
                        fma2(acc[o][i], wv.y, xv[i].y);
                    }
                }
            }
        }

        // ---- reduce: f32x2 fold -> cq fold (shfl) -> smem over (warp, rp) ----
#pragma unroll
        for (int o = 0; o < 8; o++)
#pragma unroll
            for (int i = 0; i < 8; i++) {
                float2 p = unpack2(acc[o][i]);
                float  v = p.x + p.y;
                v += __shfl_xor_sync(0xffffffffu, v, 1);
                v += __shfl_xor_sync(0xffffffffu, v, 2);
                if (cq == 0) red[warp * 8 + rp][o * 8 + i] = v;
            }
        __syncthreads();

        if (t < 128) {
            int o   = t >> 4;
            int b   = t & 15;
            int bqo = b >> 3;
            int bl_ = b & 7;
            float v = 0.f;
#pragma unroll
            for (int kk = 0; kk < 4; kk++)
#pragma unroll
                for (int r = 0; r < 8; r++)
                    v += red[(kk * 2 + bqo) * 8 + r][o * 8 + bl_];
            int og = o0 + o;
            if (og < O1_) {
                float h = v + b1[og];
                h = (h > 0.f) ? h : expm1f(h);
                g_h1t[og * 16 + b] = h;
            }
        }
    }

    grid_sync();

    // ================= STAGE 2: h2[o][b] (4 o's per block) =================
    {
        __shared__ float part2[8][16];
        int b  = t & 15;
        int sp = t >> 4;
#pragma unroll 1
        for (int sub = 0; sub < 4; sub++) {
            int o = bid * 4 + sub;
            float acc = 0.f;
#pragma unroll
            for (int k = 0; k < 32; k++) {
                int s = sp + (k << 4);
                acc = fmaf(g_h1t[(o + s) * 16 + b], W2[o * SZ_ + s], acc);
            }
            acc += __shfl_down_sync(0xffffffffu, acc, 16);
            if (lane < 16) part2[warp][lane] = acc;
            __syncthreads();
            if (t < 16) {
                float v = 0.f;
#pragma unroll
                for (int w = 0; w < 8; w++) v += part2[w][t];
                g_h2t[o * 16 + t] = v + b2[o];
            }
            __syncthreads();
        }
    }

    grid_sync();

    // ================= STAGE 3: gate[b] (block 0 only) =================
    {
        __shared__ float sl[8][16], ss[8][16];
        if (bid == 0) {
            int b = t & 15;
            int p = t >> 4;
            float al = 0.f, as_ = 0.f;
#pragma unroll
            for (int k = 0; k < 32; k++) {
                int s  = p + (k << 4);
                float hv = g_h2t[s * 16 + b];
                al  = fmaf(hv, Wl[s], al);
                as_ = fmaf(hv, Ws[s], as_);
            }
            al  += __shfl_down_sync(0xffffffffu, al, 16);
            as_ += __shfl_down_sync(0xffffffffu, as_, 16);
            if (lane < 16) { sl[warp][lane] = al; ss[warp][lane] = as_; }
            __syncthreads();
            if (t < 16) {
                float Lv = 0.f, Sv = 0.f;
#pragma unroll
                for (int w = 0; w < 8; w++) { Lv += sl[w][t]; Sv += ss[w][t]; }
                Lv += bl[0];
                Sv += bs[0];
                g_gate[t] = Lv * (1.f / (1.f + expf(-Sv)));
            }
        }
    }

    grid_sync();

    // ================= STAGE 4: out (3 float4 per thread) =================
    {
        int base = bid * 768 + t;      // 128*768 = 98304 = 16*1535*16/4
        int cq4  = base & 3;           // invariant across j (768,256 % 4 == 0)
        int c0   = 4 * cq4;

        float4 sc, sh;
        sc.x = rsqrtf(mv[c0 + 0] + EPS_) * gamma[c0 + 0];
        sc.y = rsqrtf(mv[c0 + 1] + EPS_) * gamma[c0 + 1];
        sc.z = rsqrtf(mv[c0 + 2] + EPS_) * gamma[c0 + 2];
        sc.w = rsqrtf(mv[c0 + 3] + EPS_) * gamma[c0 + 3];
        sh.x = beta[c0 + 0] - mm[c0 + 0] * sc.x;
        sh.y = beta[c0 + 1] - mm[c0 + 1] * sc.y;
        sh.z = beta[c0 + 2] - mm[c0 + 2] * sc.z;
        sh.w = beta[c0 + 3] - mm[c0 + 3] * sc.w;

#pragma unroll
        for (int j = 0; j < 3; j++) {
            int i4   = base + j * 256;
            int rest = i4 >> 2;
            int l    = rest % (L_ + 1);
            int bb   = rest / (L_ + 1);
            float g  = g_gate[bb];
            float4 xv = make_float4(0.f, 0.f, 0.f, 0.f);
            if (l < L_) xv = *(const float4*)(x + (bb * L_ + l) * 16 + c0);
            float4 r;
            r.x = (xv.x + g) * sc.x + sh.x;
            r.y = (xv.y + g) * sc.y + sh.y;
            r.z = (xv.z + g) * sc.z + sh.z;
            r.w = (xv.w + g) * sc.w + sh.w;
            ((float4*)out)[i4] = r;
        }
    }
}

// ---------------------------------------------------------------------------
extern "C" void kernel_launch(void* const* d_in, const int* in_sizes, int n_in,
                              void* d_out, int out_size) {
    const float* x     = (const float*)d_in[0];
    const float* W1    = (const float*)d_in[1];
    const float* b1    = (const float*)d_in[2];
    const float* W2    = (const float*)d_in[3];
    const float* b2    = (const float*)d_in[4];
    const float* Wl    = (const float*)d_in[5];
    const float* bl    = (const float*)d_in[6];
    const float* Ws    = (const float*)d_in[7];
    const float* bs    = (const float*)d_in[8];
    const float* gamma = (const float*)d_in[9];
    const float* beta  = (const float*)d_in[10];
    const float* mm    = (const float*)d_in[11];
    const float* mv    = (const float*)d_in[12];
    float* out = (float*)d_out;

    k_fused<<<NBLK, 256>>>(x, W1, b1, W2, b2, Wl, bl, Ws, bs,
                           gamma, beta, mm, mv, out);
}

// round 6
// speedup vs baseline: 1.5625x; 1.5625x over previous
#include <cuda_runtime.h>
#include <math.h>

#define B_   16
#define L_   1534
#define C_   16
#define SZ_  512
#define O1_  1023
#define O2_  512
#define EPS_ 1e-3f

__device__ __align__(16) float g_h1t[(O1_ + 1) * B_];   // h1 transposed: [o][b]
__device__ __align__(16) float g_h2t[O2_ * B_];         // h2 transposed: [o][b]
__device__ float g_gate[B_];

__device__ __forceinline__ void fma2(unsigned long long& d,
                                     unsigned long long a,
                                     unsigned long long b) {
    asm("fma.rn.f32x2 %0, %1, %2, %0;" : "+l"(d) : "l"(a), "l"(b));
}
__device__ __forceinline__ float2 unpack2(unsigned long long v) {
    float2 r;
    asm("mov.b64 {%0, %1}, %2;" : "=f"(r.x), "=f"(r.y) : "l"(v));
    return r;
}

// ---------------------------------------------------------------------------
// K1: h1[o][b] = elu( sum_{s,c} x[b,o+s,c] * W1[o,s,c] + b1[o] )
//
// Block: 8 o's, 256 threads = 8 warps = kh(2) x bq(4).
//   lane: cq = lane&3, rp = lane>>2. Thread: no=8 o's x nb=4 batches.
// Reduction d = rp + 8k, k in [0,65); kh halves the k range.
// acc[o][b] = one f32x2 (c01+c23 folded). Software-pipelined: iter k+1's
// x/W1 loads issue before iter k's FMA burst -> DRAM latency overlapped.
// ---------------------------------------------------------------------------
__global__ void __launch_bounds__(256) k_stage1(const float* __restrict__ x,
                                                const float* __restrict__ W1,
                                                const float* __restrict__ b1) {
    const int t    = threadIdx.x;
    const int lane = t & 31;
    const int warp = t >> 5;
    const int cq   = lane & 3;
    const int rp   = lane >> 2;
    const int bq   = warp & 3;
    const int kh   = warp >> 2;
    const int o0   = blockIdx.x * 8;
    const bool full = (o0 + 8 <= O1_);

    unsigned long long acc[8][4];
#pragma unroll
    for (int o = 0; o < 8; o++)
#pragma unroll
        for (int i = 0; i < 4; i++) acc[o][i] = 0ull;

    const int k_begin = kh ? 32 : 0;

    const float* px[4];
#pragma unroll
    for (int i = 0; i < 4; i++)
        px[i] = x + ((4 * bq + i) * L_ + o0 + rp) * 16 + 4 * cq + k_begin * 128;
    const float* pw = W1 + o0 * (SZ_ * C_) + rp * 16 + 4 * cq + k_begin * 128;

    // ---- prologue (kh=0 only), k=0, d=rp: valid o <= rp ----
    if (kh == 0) {
        ulonglong2 xv[4];
#pragma unroll
        for (int i = 0; i < 4; i++) xv[i] = *(const ulonglong2*)px[i];
#pragma unroll
        for (int o = 0; o < 8; o++) {
            if (o <= rp && (full || o0 + o < O1_)) {
                ulonglong2 wv = *(const ulonglong2*)(pw + o * 8176);
#pragma unroll
                for (int i = 0; i < 4; i++) {
                    fma2(acc[o][i], wv.x, xv[i].x);
                    fma2(acc[o][i], wv.y, xv[i].y);
                }
            }
        }
#pragma unroll
        for (int i = 0; i < 4; i++) px[i] += 128;
        pw += 128;
    }

    // ---- interior, software-pipelined double buffer ----
    // kh=0: k=1..31 (31 iters); kh=1: k=32..63 (32 iters)
    const int kcount = kh ? 32 : 31;

    ulonglong2 xv[2][4], wv[2][8];
    // preload stage 0
#pragma unroll
    for (int i = 0; i < 4; i++) xv[0][i] = *(const ulonglong2*)px[i];
#pragma unroll
    for (int o = 0; o < 8; o++) wv[0][o] = *(const ulonglong2*)(pw + o * 8176);
#pragma unroll
    for (int i = 0; i < 4; i++) px[i] += 128;
    pw += 128;

    if (full) {
#pragma unroll 2
        for (int k = 0; k < kcount; k++) {
            const int cur = k & 1, nxt = cur ^ 1;
            if (k + 1 < kcount) {
#pragma unroll
                for (int i = 0; i < 4; i++) xv[nxt][i] = *(const ulonglong2*)px[i];
#pragma unroll
                for (int o = 0; o < 8; o++) wv[nxt][o] = *(const ulonglong2*)(pw + o * 8176);
#pragma unroll
                for (int i = 0; i < 4; i++) px[i] += 128;
                pw += 128;
            }
#pragma unroll
            for (int o = 0; o < 8; o++)
#pragma unroll
                for (int i = 0; i < 4; i++) {
                    fma2(acc[o][i], wv[cur][o].x, xv[cur][i].x);
                    fma2(acc[o][i], wv[cur][o].y, xv[cur][i].y);
                }
        }
    } else {
#pragma unroll 2
        for (int k = 0; k < kcount; k++) {
            const int cur = k & 1, nxt = cur ^ 1;
            if (k + 1 < kcount) {
#pragma unroll
                for (int i = 0; i < 4; i++) xv[nxt][i] = *(const ulonglong2*)px[i];
#pragma unroll
                for (int o = 0; o < 8; o++)
                    if (o0 + o < O1_) wv[nxt][o] = *(const ulonglong2*)(pw + o * 8176);
#pragma unroll
                for (int i = 0; i < 4; i++) px[i] += 128;
                pw += 128;
            }
#pragma unroll
            for (int o = 0; o < 8; o++) {
                if (o0 + o < O1_) {
#pragma unroll
                    for (int i = 0; i < 4; i++) {
                        fma2(acc[o][i], wv[cur][o].x, xv[cur][i].x);
                        fma2(acc[o][i], wv[cur][o].y, xv[cur][i].y);
                    }
                }
            }
        }
    }

    // ---- epilogue (kh=1 only), k=64, d=512+rp: valid o > rp ----
    if (kh == 1) {
        int row = o0 + 512 + rp;
        if (row > L_ - 1) row = L_ - 1;     // clamped slots only hit masked o's
        ulonglong2 exv[4];
#pragma unroll
        for (int i = 0; i < 4; i++)
            exv[i] = *(const ulonglong2*)(x + ((4 * bq + i) * L_ + row) * 16 + 4 * cq);
#pragma unroll
        for (int o = 0; o < 8; o++) {
            if (o > rp && (full || o0 + o < O1_)) {
                ulonglong2 ewv = *(const ulonglong2*)(pw + o * 8176);
#pragma unroll
                for (int i = 0; i < 4; i++) {
                    fma2(acc[o][i], ewv.x, exv[i].x);
                    fma2(acc[o][i], ewv.y, exv[i].y);
                }
            }
        }
    }

    // ---- reduction: f32x2 fold -> cq fold (shfl) -> smem over (rp, kh) ----
    float s[8][4];
#pragma unroll
    for (int o = 0; o < 8; o++)
#pragma unroll
        for (int i = 0; i < 4; i++) {
            float2 p = unpack2(acc[o][i]);
            float v = p.x + p.y;
            v += __shfl_xor_sync(0xffffffffu, v, 1);
            v += __shfl_xor_sync(0xffffffffu, v, 2);
            s[o][i] = v;
        }

    __shared__ float red[64][36];
    if (cq == 0) {
        int contrib = warp * 8 + rp;
#pragma unroll
        for (int o = 0; o < 8; o++) {
            float4 v4 = make_float4(s[o][0], s[o][1], s[o][2], s[o][3]);
            *(float4*)&red[contrib][o * 4] = v4;
        }
    }
    __syncthreads();

    if (t < 128) {
        int o   = t >> 4;
        int b   = t & 15;
        int bqq = b >> 2;
        int bl  = b & 3;
        float v = 0.f;
#pragma unroll
        for (int k2 = 0; k2 < 2; k2++)
#pragma unroll
            for (int r = 0; r < 8; r++)
                v += red[(k2 * 4 + bqq) * 8 + r][o * 4 + bl];
        int og = o0 + o;
        if (og < O1_) {
            float h = v + b1[og];
            h = (h > 0.f) ? h : expm1f(h);
            g_h1t[og * 16 + b] = h;
        }
    }
}

// ---------------------------------------------------------------------------
// K2: h2[o][b] = sum_s h1[o+s][b] * W2[o*512+s] + b2[o]
// ---------------------------------------------------------------------------
__global__ void __launch_bounds__(256) k_stage2(const float* __restrict__ W2,
                                                const float* __restrict__ b2) {
    int o  = blockIdx.x;
    int t  = threadIdx.x;
    int b  = t & 15;
    int sp = t >> 4;

    float acc = 0.f;
#pragma unroll
    for (int k = 0; k < 32; k++) {
        int s = sp + (k << 4);
        acc = fmaf(g_h1t[(o + s) * 16 + b], W2[o * SZ_ + s], acc);
    }

    acc += __shfl_down_sync(0xffffffffu, acc, 16);

    __shared__ float part[8][16];
    int warp = t >> 5, lane = t & 31;
    if (lane < 16) part[warp][lane] = acc;
    __syncthreads();

    if (t < 16) {
        float v = 0.f;
#pragma unroll
        for (int w = 0; w < 8; w++) v += part[w][t];
        g_h2t[o * 16 + t] = v + b2[o];
    }
}

// ---------------------------------------------------------------------------
// K3: gate[b] = (dot(h2[:,b], Wl) + bl) * sigmoid(dot(h2[:,b], Ws) + bs)
// ---------------------------------------------------------------------------
__global__ void __launch_bounds__(512) k_stage3(const float* __restrict__ Wl,
                                                const float* __restrict__ bl,
                                                const float* __restrict__ Ws,
                                                const float* __restrict__ bs) {
    int b = blockIdx.x;
    int t = threadIdx.x;

    float hv  = g_h2t[t * 16 + b];
    float al  = hv * Wl[t];
    float as_ = hv * Ws[t];

#pragma unroll
    for (int off = 16; off; off >>= 1) {
        al  += __shfl_down_sync(0xffffffffu, al, off);
        as_ += __shfl_down_sync(0xffffffffu, as_, off);
    }

    __shared__ float sl[16], ss[16];
    int warp = t >> 5;
    int lane = t & 31;
    if (lane == 0) { sl[warp] = al; ss[warp] = as_; }
    __syncthreads();

    if (t == 0) {
        float Lv = 0.f, Sv = 0.f;
#pragma unroll
        for (int w = 0; w < 16; w++) { Lv += sl[w]; Sv += ss[w]; }
        Lv += bl[0];
        Sv += bs[0];
        g_gate[b] = Lv * (1.f / (1.f + expf(-Sv)));
    }
}

// ---------------------------------------------------------------------------
// K4: out = ((l<L ? x : 0) + gate[b] - mm[c]) * rsqrt(var[c]+eps)*gamma[c] + beta[c]
// 384 blocks x 256 threads x exactly 1 float4 each (full-chip single wave).
// ---------------------------------------------------------------------------
__global__ void __launch_bounds__(256) k_stage4(const float* __restrict__ x,
                                                const float* __restrict__ gamma,
                                                const float* __restrict__ beta,
                                                const float* __restrict__ mm,
                                                const float* __restrict__ mv,
                                                float* __restrict__ out) {
    int i4   = blockIdx.x * 256 + threadIdx.x;   // [0, 98304)
    int cq   = i4 & 3;
    int c0   = 4 * cq;
    int rest = i4 >> 2;
    int l    = rest % (L_ + 1);
    int b    = rest / (L_ + 1);

    float4 xv = make_float4(0.f, 0.f, 0.f, 0.f);
    if (l < L_) xv = *(const float4*)(x + (b * L_ + l) * 16 + c0);

    float g = g_gate[b];
    float4 r;
    float sx = rsqrtf(mv[c0 + 0] + EPS_) * gamma[c0 + 0];
    float sy = rsqrtf(mv[c0 + 1] + EPS_) * gamma[c0 + 1];
    float sz = rsqrtf(mv[c0 + 2] + EPS_) * gamma[c0 + 2];
    float sw = rsqrtf(mv[c0 + 3] + EPS_) * gamma[c0 + 3];
    r.x = (xv.x + g - mm[c0 + 0]) * sx + beta[c0 + 0];
    r.y = (xv.y + g - mm[c0 + 1]) * sy + beta[c0 + 1];
    r.z = (xv.z + g - mm[c0 + 2]) * sz + beta[c0 + 2];
    r.w = (xv.w + g - mm[c0 + 3]) * sw + beta[c0 + 3];

    ((float4*)out)[i4] = r;
}

// ---------------------------------------------------------------------------
extern "C" void kernel_launch(void* const* d_in, const int* in_sizes, int n_in,
                              void* d_out, int out_size) {
    const float* x     = (const float*)d_in[0];
    const float* W1    = (const float*)d_in[1];
    const float* b1    = (const float*)d_in[2];
    const float* W2    = (const float*)d_in[3];
    const float* b2    = (const float*)d_in[4];
    const float* Wl    = (const float*)d_in[5];
    const float* bl    = (const float*)d_in[6];
    const float* Ws    = (const float*)d_in[7];
    const float* bs    = (const float*)d_in[8];
    const float* gamma = (const float*)d_in[9];
    const float* beta  = (const float*)d_in[10];
    const float* mm    = (const float*)d_in[11];
    const float* mv    = (const float*)d_in[12];
    float* out = (float*)d_out;

    k_stage1<<<(O1_ + 7) / 8, 256>>>(x, W1, b1);
    k_stage2<<<O2_, 256>>>(W2, b2);
    k_stage3<<<B_, 512>>>(Wl, bl, Ws, bs);
    k_stage4<<<384, 256>>>(x, gamma, beta, mm, mv, out);
}